// round 8
// baseline (speedup 1.0000x reference)
#include <cuda_runtime.h>
#include <cuda_fp16.h>

#define RES 256
#define NA  180
#define NB  4
#define PW  257            // x0p in [0,256]
#define PH  257            // y0p in [0,256]
#define NPIX (PH*PW)
#define NOUT (NB*NA*RES)

// Corner-packed fp16 images, batches interleaved INSIDE each half2 so the
// bilerp runs as half2 SIMD over batch pairs. 32 bytes per padded pixel:
//   w0 = h2(b0.v00, b1.v00)   w4 = h2(b2.v00, b3.v00)
//   w1 = h2(b0.v01, b1.v01)   w5 = h2(b2.v01, b3.v01)
//   w2 = h2(b0.v10, b1.v10)   w6 = h2(b2.v10, b3.v10)
//   w3 = h2(b0.v11, b1.v11)   w7 = h2(b2.v11, b3.v11)
// vXY = img[y0+X][x0+Y], OOB -> 0 (zero border = reference's validity mask).
struct __align__(32) Px { uint4 a, b; };
__device__ Px g_P[NPIX];

__device__ __forceinline__ unsigned pack2(float a, float b) {
    __half2 h = __floats2half2_rn(a, b);
    return *reinterpret_cast<unsigned*>(&h);
}
__device__ __forceinline__ __half2 as_h2(unsigned u) {
    return *reinterpret_cast<__half2*>(&u);
}

// 256-bit global load (sm_100+).
__device__ __forceinline__ void ldg256(const Px* p, uint4& a, uint4& b) {
    asm volatile("ld.global.nc.v8.u32 {%0,%1,%2,%3,%4,%5,%6,%7}, [%8];"
                 : "=r"(a.x), "=r"(a.y), "=r"(a.z), "=r"(a.w),
                   "=r"(b.x), "=r"(b.y), "=r"(b.z), "=r"(b.w)
                 : "l"(p));
}

// Prep: build corner-packed array AND zero the output (radon adds atomically).
__global__ __launch_bounds__(256) void prep_kernel(const float* __restrict__ imgs,
                                                   float* __restrict__ out)
{
    int idx = blockIdx.x * blockDim.x + threadIdx.x;
    if (idx < NOUT) out[idx] = 0.0f;
    if (idx >= NPIX) return;
    const int xp = idx % PW;
    const int yp = idx / PW;
    const int yt = yp - 1, yb = yp;
    const int xl = xp - 1, xr = xp;

    float v[NB][4];
    #pragma unroll
    for (int b = 0; b < NB; ++b) {
        const float* im = imgs + (size_t)b * RES * RES;
        const bool vt = ((unsigned)yt < RES), vb = ((unsigned)yb < RES);
        const bool vl = ((unsigned)xl < RES), vr = ((unsigned)xr < RES);
        v[b][0] = (vt && vl) ? im[yt * RES + xl] : 0.0f;   // v00
        v[b][1] = (vt && vr) ? im[yt * RES + xr] : 0.0f;   // v01
        v[b][2] = (vb && vl) ? im[yb * RES + xl] : 0.0f;   // v10
        v[b][3] = (vb && vr) ? im[yb * RES + xr] : 0.0f;   // v11
    }
    Px px;
    px.a.x = pack2(v[0][0], v[1][0]);   // v00 of b0,b1
    px.a.y = pack2(v[0][1], v[1][1]);   // v01
    px.a.z = pack2(v[0][2], v[1][2]);   // v10
    px.a.w = pack2(v[0][3], v[1][3]);   // v11
    px.b.x = pack2(v[2][0], v[3][0]);
    px.b.y = pack2(v[2][1], v[3][1]);
    px.b.z = pack2(v[2][2], v[3][2]);
    px.b.w = pack2(v[2][3], v[3][3]);
    g_P[idx] = px;
}

// Bilerp for a batch pair, fully in half2 SIMD; returns float2 sample.
__device__ __forceinline__ float2 bilerp_h2(const uint4& q,
                                            __half2 wx2, __half2 wy2)
{
    const __half2 v00 = as_h2(q.x), v01 = as_h2(q.y);
    const __half2 v10 = as_h2(q.z), v11 = as_h2(q.w);
    const __half2 top = __hfma2(wx2, __hsub2(v01, v00), v00);
    const __half2 bot = __hfma2(wx2, __hsub2(v11, v10), v10);
    const __half2 smp = __hfma2(wy2, __hsub2(bot, top), top);
    return __half22float2(smp);
}

// Block = 128 threads (4 warps). Warp tile: 8 rays x 4 t-phases.
// Grid: (angle, ray_group 0..7, t_half 0..1).
// Each block: 32 rays x 128 t-steps (t = th*128 + 4*i + t4, i in [0,32)).
// Inner loop chunked by 4 with all 4 LDG.256 issued back-to-back -> MLP>=4.
__global__ __launch_bounds__(128) void radon_kernel(
    const float* __restrict__ angles,
    const float* __restrict__ rays,
    float* __restrict__ out)
{
    const int tid  = threadIdx.x;
    const int lane = tid & 31;
    const int warp = tid >> 5;        // 0..3
    const int r8   = lane & 7;        // ray within warp tile
    const int t4   = lane >> 3;       // t-phase 0..3
    const int a    = blockIdx.x;      // angle
    const int rg   = blockIdx.y;      // ray group 0..7
    const int th   = blockIdx.z;      // t half 0..1
    const int ray  = rg * 32 + warp * 8 + r8;

    const float4 r4 = __ldg(reinterpret_cast<const float4*>(rays) + ray);
    float s, c;
    sincosf(__ldg(angles + a), &s, &c);

    const float rsx = r4.x * c - r4.y * s;
    const float rsy = r4.x * s + r4.y * c;
    const float dx  = (r4.z * c - r4.w * s) - rsx;
    const float dy  = (r4.z * s + r4.w * c) - rsy;

    const float inv_n = 1.0f / RES;
    const float t0 = (float)(th * 128 + t4) + 0.5f;
    // +128.5 folds image-center offset (127.5) and the +1 padding shift.
    float gx = rsx + 128.5f + dx * inv_n * t0;
    float gy = rsy + 128.5f + dy * inv_n * t0;
    const float sx4 = dx * inv_n * 4.0f;
    const float sy4 = dy * inv_n * 4.0f;

    float acc0 = 0.f, acc1 = 0.f, acc2 = 0.f, acc3 = 0.f;

    #pragma unroll 2
    for (int i = 0; i < 8; ++i) {
        float wxr[4], wyr[4];
        uint4 qa[4], qb[4];

        // Phase 1: 4 addresses + 4 back-to-back 256-bit loads (MLP = 4).
        #pragma unroll
        for (int j = 0; j < 4; ++j) {
            const float fx = gx + sx4 * (float)j;
            const float fy = gy + sy4 * (float)j;
            const int x0 = __float2int_rd(fx);
            const int y0 = __float2int_rd(fy);
            wxr[j] = fx - (float)x0;
            wyr[j] = fy - (float)y0;
            ldg256(g_P + (y0 * PW + x0), qa[j], qb[j]);
        }

        // Phase 2: consume.
        #pragma unroll
        for (int j = 0; j < 4; ++j) {
            const __half2 wx2 = __floats2half2_rn(wxr[j], wxr[j]);
            const __half2 wy2 = __floats2half2_rn(wyr[j], wyr[j]);
            const float2 s01 = bilerp_h2(qa[j], wx2, wy2);
            const float2 s23 = bilerp_h2(qb[j], wx2, wy2);
            acc0 += s01.x;  acc1 += s01.y;
            acc2 += s23.x;  acc3 += s23.y;
        }

        gx += sx4 * 4.0f;
        gy += sy4 * 4.0f;
    }

    // Reduce the 4 t-phases of each ray (lanes l, l+8, l+16, l+24).
    acc0 += __shfl_xor_sync(0xFFFFFFFFu, acc0, 8);
    acc0 += __shfl_xor_sync(0xFFFFFFFFu, acc0, 16);
    acc1 += __shfl_xor_sync(0xFFFFFFFFu, acc1, 8);
    acc1 += __shfl_xor_sync(0xFFFFFFFFu, acc1, 16);
    acc2 += __shfl_xor_sync(0xFFFFFFFFu, acc2, 8);
    acc2 += __shfl_xor_sync(0xFFFFFFFFu, acc2, 16);
    acc3 += __shfl_xor_sync(0xFFFFFFFFu, acc3, 8);
    acc3 += __shfl_xor_sync(0xFFFFFFFFu, acc3, 16);

    if (t4 == 0) {
        const float step = (r4.w - r4.y) * inv_n;   // L / n_steps
        const int base = a * RES + ray;
        atomicAdd(out + 0 * NA * RES + base, acc0 * step);
        atomicAdd(out + 1 * NA * RES + base, acc1 * step);
        atomicAdd(out + 2 * NA * RES + base, acc2 * step);
        atomicAdd(out + 3 * NA * RES + base, acc3 * step);
    }
}

extern "C" void kernel_launch(void* const* d_in, const int* in_sizes, int n_in,
                              void* d_out, int out_size)
{
    const float* imgs   = (const float*)d_in[0];   // [4,256,256]
    const float* angles = (const float*)d_in[1];   // [180]
    const float* rays   = (const float*)d_in[2];   // [256,4]
    float* out          = (float*)d_out;           // [4,180,256]

    const int prep_threads = (NOUT > NPIX ? NOUT : NPIX);
    prep_kernel<<<(prep_threads + 255) / 256, 256>>>(imgs, out);

    dim3 grid(NA, 8, 2);
    radon_kernel<<<grid, 128>>>(angles, rays, out);
}